// round 6
// baseline (speedup 1.0000x reference)
#include <cuda_runtime.h>
#include <math.h>
#include <stdint.h>

#define D 128
#define NRELS 16
#define MAXN 50000

// ---------------- scratch (__device__ globals: allocation-free rule) -------
__device__ float g_hall[(size_t)NRELS * MAXN * D];   // [r][n][d]
__device__ float g_glog[(size_t)MAXN * NRELS];       // [n][r]
__device__ float g_h1[(size_t)MAXN * D];             // layer-0 out
__device__ float g_atf[(size_t)MAXN * D];            // h rounded to tf32
__device__ float g_wt[(size_t)NRELS * D * D];        // W^T tf32-rounded [r][e][d]
__device__ float g_lwt[(size_t)D * D];               // loop_w^T tf32-rounded

__device__ __forceinline__ float f2tf32f(float x) {
    uint32_t y;
    asm("cvt.rna.tf32.f32 %0, %1;" : "=r"(y) : "f"(x));
    return __uint_as_float(y);
}
__device__ __forceinline__ uint32_t smem_u32(const void* p) {
    uint32_t a;
    asm("{ .reg .u64 t; cvta.to.shared.u64 t, %1; cvt.u32.u64 %0, t; }"
        : "=r"(a) : "l"(p));
    return a;
}
__device__ __forceinline__ void cp16(uint32_t dst, const void* src, int srcBytes) {
    asm volatile("cp.async.cg.shared.global [%0], [%1], 16, %2;"
                 :: "r"(dst), "l"(src), "r"(srcBytes) : "memory");
}
#define CP_COMMIT() asm volatile("cp.async.commit_group;" ::: "memory")
#define CP_WAIT0()  asm volatile("cp.async.wait_group 0;" ::: "memory")

// ---------------------------------------------------------------------------
// tf32 GEMM, 256 threads, BM=256, BN=128, 8 warps (4m x 2n), warp tile 64x64.
// C[r] = A @ B[r] for r in [rBase, rBase+Rper). A resident in SMEM (full K),
// B streamed in K-half chunks (64 k) with cp.async double buffering.
// Warp tile 64x64 -> 8 MAC/smem-byte (vs 5.3 at 64x32): crossbar-bound fix.
// ---------------------------------------------------------------------------
#define SROW_A 132
#define SROW_B 68
#define SM_A_BYTES (256 * SROW_A * 4)     // 135168
#define SM_BCHUNK  (128 * SROW_B * 4)     // 34816
#define GEMM_SMEM  (SM_A_BYTES + 2 * SM_BCHUNK)   // 204800

__global__ __launch_bounds__(256, 1)
void gemm_v3(const float* __restrict__ A, const float* __restrict__ B,
             float* __restrict__ C0, size_t strideC, int Rper, int M,
             const float* __restrict__ bias)
{
    extern __shared__ char smem[];
    const uint32_t sA  = smem_u32(smem);
    const uint32_t sB0 = sA + SM_A_BYTES;
    const uint32_t sB1 = sB0 + SM_BCHUNK;

    const int tid  = threadIdx.x;
    const int lane = tid & 31;
    const int wid  = tid >> 5;
    const int warp_m = wid >> 1;        // 0..3 (64 rows each)
    const int warp_n = wid & 1;         // 0..1 (64 cols each)
    const int g = lane >> 2;            // 0..7
    const int c = lane & 3;             // 0..3
    const int mBase = blockIdx.x * 256;
    const int rBase = blockIdx.y * Rper;
    const int nChunks = 2 * Rper;

    // ---- stage A (256 x 128, full K): 8192 16B-chunks, 32 per thread ------
#pragma unroll
    for (int it = 0; it < 32; it++) {
        int i = tid + it * 256;
        int row = i >> 5;               // 0..255
        int c4  = (i & 31) * 4;
        bool valid = (mBase + row) < M;
        const float* src = A + (valid ? ((size_t)(mBase + row) * D + c4) : 0);
        cp16(sA + (uint32_t)(row * SROW_A + c4) * 4, src, valid ? 16 : 0);
    }
    // ---- stage B chunk 0: 2048 chunks, 8 per thread ------------------------
    {
        const float* Bc = B + (size_t)rBase * D * D;   // half 0: k 0..63
#pragma unroll
        for (int it = 0; it < 8; it++) {
            int i = tid + it * 256;
            int row = i >> 4;           // 0..127
            int c4  = (i & 15) * 4;     // 0..60
            cp16(sB0 + (uint32_t)(row * SROW_B + c4) * 4,
                 Bc + (size_t)row * D + c4, 16);
        }
    }
    CP_COMMIT();
    CP_WAIT0();
    __syncthreads();

    const uint32_t aBase = sA + (uint32_t)(warp_m * 64) * SROW_A * 4;

    float acc[4][8][4];

    for (int j = 0; j < nChunks; j++) {
        const uint32_t sCur = (j & 1) ? sB1 : sB0;

        if (j + 1 < nChunks) {   // prefetch chunk j+1
            const uint32_t sNxt = (j & 1) ? sB0 : sB1;
            const int r1 = rBase + ((j + 1) >> 1);
            const int h1 = ((j + 1) & 1) * 64;
            const float* Bc = B + (size_t)r1 * D * D + h1;
#pragma unroll
            for (int it = 0; it < 8; it++) {
                int i = tid + it * 256;
                int row = i >> 4;
                int c4  = (i & 15) * 4;
                cp16(sNxt + (uint32_t)(row * SROW_B + c4) * 4,
                     Bc + (size_t)row * D + c4, 16);
            }
            CP_COMMIT();
        }

        if (!(j & 1)) {   // new relation -> clear accumulators
#pragma unroll
            for (int mi = 0; mi < 4; mi++)
#pragma unroll
                for (int ni = 0; ni < 8; ni++)
#pragma unroll
                    for (int f = 0; f < 4; f++) acc[mi][ni][f] = 0.f;
        }

        // ---- compute 8 k8-steps against this chunk -------------------------
        const int kbGlob = (j & 1) * 64;
        const uint32_t bBase = sCur + (uint32_t)(warp_n * 64) * SROW_B * 4;
#pragma unroll
        for (int kc = 0; kc < 8; kc++) {
            const int kbA = kbGlob + kc * 8;
            const int kbB = kc * 8;
            uint32_t af[4][4], bf[8][2];
#pragma unroll
            for (int mi = 0; mi < 4; mi++) {
                uint32_t a0 = aBase + (uint32_t)((mi * 16 + g) * SROW_A + kbA + c) * 4;
                asm volatile("ld.shared.b32 %0, [%1];"    : "=r"(af[mi][0]) : "r"(a0));
                asm volatile("ld.shared.b32 %0, [%1+16];" : "=r"(af[mi][2]) : "r"(a0));
                uint32_t a1 = a0 + 8u * SROW_A * 4u;
                asm volatile("ld.shared.b32 %0, [%1];"    : "=r"(af[mi][1]) : "r"(a1));
                asm volatile("ld.shared.b32 %0, [%1+16];" : "=r"(af[mi][3]) : "r"(a1));
            }
#pragma unroll
            for (int ni = 0; ni < 8; ni++) {
                uint32_t b0 = bBase + (uint32_t)((ni * 8 + g) * SROW_B + kbB + c) * 4;
                asm volatile("ld.shared.b32 %0, [%1];"    : "=r"(bf[ni][0]) : "r"(b0));
                asm volatile("ld.shared.b32 %0, [%1+16];" : "=r"(bf[ni][1]) : "r"(b0));
            }
#pragma unroll
            for (int mi = 0; mi < 4; mi++)
#pragma unroll
                for (int ni = 0; ni < 8; ni++) {
                    asm volatile(
                        "mma.sync.aligned.m16n8k8.row.col.f32.tf32.tf32.f32 "
                        "{%0,%1,%2,%3}, {%4,%5,%6,%7}, {%8,%9}, {%0,%1,%2,%3};\n"
                        : "+f"(acc[mi][ni][0]), "+f"(acc[mi][ni][1]),
                          "+f"(acc[mi][ni][2]), "+f"(acc[mi][ni][3])
                        : "r"(af[mi][0]), "r"(af[mi][1]),
                          "r"(af[mi][2]), "r"(af[mi][3]),
                          "r"(bf[ni][0]), "r"(bf[ni][1]));
                }
        }

        if (j & 1) {   // relation complete -> epilogue
            const int r = rBase + (j >> 1);
            float* C = C0 + (size_t)r * strideC;
#pragma unroll
            for (int mi = 0; mi < 4; mi++) {
                const int row0 = mBase + warp_m * 64 + mi * 16 + g;
                const int row1 = row0 + 8;
#pragma unroll
                for (int ni = 0; ni < 8; ni++) {
                    const int col = warp_n * 64 + ni * 8 + c * 2;
                    float bx = 0.f, by = 0.f;
                    if (bias != nullptr) { bx = bias[col]; by = bias[col + 1]; }
                    if (row0 < M)
                        *(float2*)(C + (size_t)row0 * D + col) =
                            make_float2(acc[mi][ni][0] + bx, acc[mi][ni][1] + by);
                    if (row1 < M)
                        *(float2*)(C + (size_t)row1 * D + col) =
                            make_float2(acc[mi][ni][2] + bx, acc[mi][ni][3] + by);
                }
            }
        }

        if (j + 1 < nChunks) {
            CP_WAIT0();        // chunk j+1 landed
            __syncthreads();   // all warps done with chunk j's buffer
        }
    }
}

// ---------------------------------------------------------------------------
// rounding kernels (fp32 -> tf32-rounded fp32 bits)
// ---------------------------------------------------------------------------
__global__ void round_kernel(const float* __restrict__ x, float* __restrict__ y,
                             size_t n)
{
    size_t i = (size_t)blockIdx.x * blockDim.x + threadIdx.x;
    if (i < n) y[i] = f2tf32f(x[i]);
}

// W[r][d][e] -> out[r][e][d], tf32-rounded
__global__ void round_wT_kernel(const float* __restrict__ W,
                                float* __restrict__ out, int R)
{
    int i = blockIdx.x * blockDim.x + threadIdx.x;
    if (i >= R * D * D) return;
    int r = i / (D * D);
    int e = (i / D) & (D - 1);
    int d = i & (D - 1);
    out[i] = f2tf32f(W[(size_t)r * D * D + (size_t)d * D + e]);
}

// ---------------------------------------------------------------------------
// gate logits: glog[n][r] = dot(h[n], gw[r]); one warp per node
// ---------------------------------------------------------------------------
__global__ void glog_kernel(const float* __restrict__ h, const float* __restrict__ gw,
                            int Nn)
{
    int warp = (int)((blockIdx.x * blockDim.x + threadIdx.x) >> 5);
    int lane = threadIdx.x & 31;
    if (warp >= Nn) return;
    float4 hv = ((const float4*)(h + (size_t)warp * D))[lane];
    float mine = 0.f;
#pragma unroll
    for (int r = 0; r < NRELS; r++) {
        float4 gv = ((const float4*)(gw + r * D))[lane];
        float dot = hv.x * gv.x + hv.y * gv.y + hv.z * gv.z + hv.w * gv.w;
#pragma unroll
        for (int off = 16; off > 0; off >>= 1)
            dot += __shfl_down_sync(0xffffffffu, dot, off);
        dot = __shfl_sync(0xffffffffu, dot, 0);
        if (lane == r) mine = dot;
    }
    if (lane < NRELS) g_glog[(size_t)warp * NRELS + lane] = mine;
}

// ---------------------------------------------------------------------------
// Edge scatter: 8 edges per warp (MLP=8); red.global.add.v4.f32
// ---------------------------------------------------------------------------
#define EPW 8
__global__ void edge_kernel(const int* __restrict__ src, const int* __restrict__ dst,
                            const int* __restrict__ rel, const float* __restrict__ norm,
                            float* __restrict__ out, int E, int Nn)
{
    int warp = (int)((blockIdx.x * blockDim.x + threadIdx.x) >> 5);
    int lane = threadIdx.x & 31;
    int base = warp * EPW;
    if (base >= E) return;

    float4 v[EPW];
    float g[EPW];
    int dv[EPW];
    int cnt = min(EPW, E - base);
#pragma unroll
    for (int i = 0; i < EPW; i++) {
        if (i >= cnt) break;
        int e = base + i;
        int s = __ldg(src + e);
        dv[i] = __ldg(dst + e);
        int r = __ldg(rel + e);
        float nm = __ldg(norm + e);
        float gl = g_glog[(size_t)s * NRELS + r];
        g[i] = nm / (1.f + expf(-gl));
        v[i] = ((const float4*)(g_hall + ((size_t)r * Nn + s) * D))[lane];
    }
#pragma unroll
    for (int i = 0; i < EPW; i++) {
        if (i >= cnt) break;
        float* o = out + (size_t)dv[i] * D + lane * 4;
        asm volatile("red.global.add.v4.f32 [%0], {%1,%2,%3,%4};"
                     :: "l"(o), "f"(v[i].x * g[i]), "f"(v[i].y * g[i]),
                        "f"(v[i].z * g[i]), "f"(v[i].w * g[i])
                     : "memory");
    }
}

__global__ void relu_kernel(float* __restrict__ x, size_t n)
{
    size_t i = (size_t)blockIdx.x * blockDim.x + threadIdx.x;
    if (i < n) x[i] = fmaxf(x[i], 0.f);
}

// ---------------------------------------------------------------------------
static void run_layer(const float* hin, const float* W, const float* bias,
                      const float* lw, const float* gw,
                      const int* src, const int* dst, const int* rel,
                      const float* norm,
                      float* hall_ptr, float* hout,
                      float* atf, float* wt, float* lwt,
                      int Nn, int E, bool apply_relu)
{
    const int mtiles = (Nn + 255) / 256;
    const size_t nElem = (size_t)Nn * D;

    round_kernel<<<(int)((nElem + 255) / 256), 256>>>(hin, atf, nElem);
    round_wT_kernel<<<(NRELS * D * D + 255) / 256, 256>>>(W, wt, NRELS);
    round_wT_kernel<<<(D * D + 255) / 256, 256>>>(lw, lwt, 1);

    // hall[r] = h @ W[r] : grid (mtiles, 2), 8 relations per CTA
    gemm_v3<<<dim3(mtiles, 2), 256, GEMM_SMEM>>>(atf, wt, hall_ptr,
                                                 (size_t)Nn * D, NRELS / 2, Nn,
                                                 nullptr);
    // out = h @ loop_w + bias
    gemm_v3<<<dim3(mtiles, 1), 256, GEMM_SMEM>>>(atf, lwt, hout, 0, 1, Nn, bias);

    glog_kernel<<<(Nn * 32 + 255) / 256, 256>>>(hin, gw, Nn);

    int warps = (E + EPW - 1) / EPW;
    edge_kernel<<<(warps * 32 + 255) / 256, 256>>>(src, dst, rel, norm, hout, E, Nn);

    if (apply_relu)
        relu_kernel<<<(int)((nElem + 255) / 256), 256>>>(hout, nElem);
}

extern "C" void kernel_launch(void* const* d_in, const int* in_sizes, int n_in,
                              void* d_out, int out_size)
{
    const float* h    = (const float*)d_in[0];
    const float* norm = (const float*)d_in[1];
    const float* W0   = (const float*)d_in[2];
    const float* b0   = (const float*)d_in[3];
    const float* lw0  = (const float*)d_in[4];
    const float* gw0  = (const float*)d_in[5];
    const float* W1   = (const float*)d_in[6];
    const float* b1   = (const float*)d_in[7];
    const float* lw1  = (const float*)d_in[8];
    const float* gw1  = (const float*)d_in[9];
    const int*   src  = (const int*)d_in[10];
    const int*   dst  = (const int*)d_in[11];
    const int*   rel  = (const int*)d_in[12];
    float* out = (float*)d_out;

    int Nn = in_sizes[0] / D;
    int E  = in_sizes[10];

    cudaFuncSetAttribute(gemm_v3, cudaFuncAttributeMaxDynamicSharedMemorySize,
                         GEMM_SMEM);

    float *hall_ptr, *h1_ptr, *atf, *wt, *lwt;
    cudaGetSymbolAddress((void**)&hall_ptr, g_hall);
    cudaGetSymbolAddress((void**)&h1_ptr, g_h1);
    cudaGetSymbolAddress((void**)&atf, g_atf);
    cudaGetSymbolAddress((void**)&wt, g_wt);
    cudaGetSymbolAddress((void**)&lwt, g_lwt);

    run_layer(h, W0, b0, lw0, gw0, src, dst, rel, norm, hall_ptr, h1_ptr,
              atf, wt, lwt, Nn, E, true);
    run_layer(h1_ptr, W1, b1, lw1, gw1, src, dst, rel, norm, hall_ptr, out,
              atf, wt, lwt, Nn, E, false);
}